// round 2
// baseline (speedup 1.0000x reference)
#include <cuda_runtime.h>
#include <math.h>

#define NB 16
#define T1V 800
#define T2V 200

typedef unsigned long long ull;

// Intermediates (no allocation allowed -> __device__ globals)
__device__ float g_kh   [NB*512*200];     // key conv1 output (post-relu)
__device__ float g_kpart[4*NB*80*200];    // key conv2 split-K partials (no bias)
__device__ float g_qh1  [NB*160*800];     // query conv1 output (post-relu)
__device__ float g_qh2  [NB*80*800];      // query conv2 output (post-relu)
__device__ float g_q    [NB*80*800];      // query encoder output

// Packed dual-FMA (sm_103a): d.lo += a.lo*b.lo ; d.hi += a.hi*b.hi
#define FFMA2(d, a, b) asm("fma.rn.f32x2 %0, %1, %2, %0;" : "+l"(d) : "l"(a), "l"(b))
#define UNPACK2(lo, hi, p) asm("mov.b64 {%0, %1}, %2;" : "=f"(lo), "=f"(hi) : "l"(p))

// Implicit-im2col conv-as-GEMM, f32x2-packed on N, double-buffered smem.
//   Y[b, m, t] = bias[m] + sum_{cin,kk} W[m, cin, kk] * X[b, cin, t+kk-PAD]
// GEMM: M = COUT, N = NB*T, K = CIN*KW (kappa = kk*CIN + cin).
// 256 threads as 16(tx) x 16(ty). BM = 16*TM, BN = 32*TNP (TNP packed col-pairs
// per thread), BK = 16. A stored in smem pre-duplicated (float2{w,w}) so the
// inner loop is LDS64/128 + FFMA2 only.
// SPLITK: blockIdx.z selects K-chunk [z*KTOT, (z+1)*KTOT); output goes to
// partial buffer z (no bias/relu), reduced later in attn_final.
template<int CIN, int COUT, int KW, int PAD, bool RELU, bool SPLITK,
         int TM, int TNP, int T, int KTOT>
__global__ __launch_bounds__(256)
void conv_gemm(const float* __restrict__ W, const float* __restrict__ bias,
               const float* __restrict__ X, float* __restrict__ Y)
{
    constexpr int BM = 16 * TM, BN = 32 * TNP, BK = 16;
    constexpr int KFULL = CIN * KW;
    constexpr int LA = (BK * BM) / 256;
    constexpr int LB = (BK * BN) / 256;
    constexpr int NK = KTOT / BK;

    __shared__ __align__(16) float2 As2[2][BK][BM];   // duplicated pairs
    __shared__ __align__(16) float  Bs [2][BK][BN];

    const int tid = threadIdx.x;
    const int tx  = tid & 15, ty = tid >> 4;
    const int n0  = blockIdx.x * BN;
    const int m0  = blockIdx.y * BM;
    const int kbase = SPLITK ? blockIdx.z * KTOT : 0;

    // Per-thread B column decode (loop-invariant pieces only).
    int b_t[LB], b_row[LB];
#pragma unroll
    for (int s = 0; s < LB; s++) {
        int i  = tid + s * 256;
        int gn = n0 + (i & (BN - 1));
        int bb = gn / T;
        b_t[s]   = gn - bb * T;
        b_row[s] = bb * CIN * T;
    }

    ull acc[TM][TNP];
#pragma unroll
    for (int i = 0; i < TM; i++)
#pragma unroll
        for (int j = 0; j < TNP; j++) acc[i][j] = 0ull;

    float aR[LA], bR[LB];

    // ---- prologue: load K-tile 0 ----
#pragma unroll
    for (int s = 0; s < LA; s++) {
        int i   = tid + s * 256;
        int kap = kbase + (i & (BK - 1));
        int kk  = kap / CIN;
        int cin = kap - kk * CIN;
        aR[s] = W[(m0 + (i >> 4)) * KFULL + cin * KW + kk];
    }
#pragma unroll
    for (int s = 0; s < LB; s++) {
        int i   = tid + s * 256;
        int kap = kbase + i / BN;
        int kk  = kap / CIN;
        int cin = kap - kk * CIN;
        int tin = b_t[s] + kk - PAD;
        float v = 0.f;
        if ((unsigned)tin < (unsigned)T) v = X[b_row[s] + cin * T + tin];
        bR[s] = v;
    }
#pragma unroll
    for (int s = 0; s < LA; s++) {
        int i = tid + s * 256;
        As2[0][i & (BK - 1)][i >> 4] = make_float2(aR[s], aR[s]);
    }
#pragma unroll
    for (int s = 0; s < LB; s++) {
        int i = tid + s * 256;
        Bs[0][i / BN][i & (BN - 1)] = bR[s];
    }
    __syncthreads();

    int buf = 0;
    for (int kt = 0; kt < NK; kt++) {
        // prefetch next tile into registers (overlaps with compute)
        if (kt + 1 < NK) {
            const int k0 = (kt + 1) * BK;
#pragma unroll
            for (int s = 0; s < LA; s++) {
                int i   = tid + s * 256;
                int kap = kbase + k0 + (i & (BK - 1));
                int kk  = kap / CIN;
                int cin = kap - kk * CIN;
                aR[s] = W[(m0 + (i >> 4)) * KFULL + cin * KW + kk];
            }
#pragma unroll
            for (int s = 0; s < LB; s++) {
                int i   = tid + s * 256;
                int kap = kbase + k0 + i / BN;
                int kk  = kap / CIN;
                int cin = kap - kk * CIN;
                int tin = b_t[s] + kk - PAD;
                float v = 0.f;
                if ((unsigned)tin < (unsigned)T) v = X[b_row[s] + cin * T + tin];
                bR[s] = v;
            }
        }

        // compute current tile: pure LDS + FFMA2
#pragma unroll
        for (int kl = 0; kl < BK; kl++) {
            const ull* Ap = reinterpret_cast<const ull*>(&As2[buf][kl][ty * TM]);
            const ull* Bp = reinterpret_cast<const ull*>(&Bs[buf][kl][tx * TNP * 2]);
            ull a[TM], b[TNP];
#pragma unroll
            for (int i = 0; i < TM; i++) a[i] = Ap[i];
#pragma unroll
            for (int j = 0; j < TNP; j++) b[j] = Bp[j];
#pragma unroll
            for (int i = 0; i < TM; i++)
#pragma unroll
                for (int j = 0; j < TNP; j++)
                    FFMA2(acc[i][j], a[i], b[j]);
        }

        if (kt + 1 < NK) {
#pragma unroll
            for (int s = 0; s < LA; s++) {
                int i = tid + s * 256;
                As2[buf ^ 1][i & (BK - 1)][i >> 4] = make_float2(aR[s], aR[s]);
            }
#pragma unroll
            for (int s = 0; s < LB; s++) {
                int i = tid + s * 256;
                Bs[buf ^ 1][i / BN][i & (BN - 1)] = bR[s];
            }
            __syncthreads();
        }
        buf ^= 1;
    }

    // ---- epilogue ----
    float* Yp = SPLITK ? Y + blockIdx.z * (COUT * NB * T) : Y;
#pragma unroll
    for (int j = 0; j < TNP; j++) {
        float lo[TM], hi[TM];
#pragma unroll
        for (int i = 0; i < TM; i++) UNPACK2(lo[i], hi[i], acc[i][j]);

        int gn0 = n0 + tx * TNP * 2 + 2 * j;
#pragma unroll
        for (int h = 0; h < 2; h++) {
            int gn = gn0 + h;
            int bb = gn / T;
            int tt = gn - bb * T;
#pragma unroll
            for (int i = 0; i < TM; i++) {
                int m = m0 + ty * TM + i;
                float v = (h ? hi[i] : lo[i]);
                if (!SPLITK) {
                    v += bias[m];
                    if (RELU) v = fmaxf(v, 0.f);
                }
                Yp[(bb * COUT + m) * T + tt] = v;
            }
        }
    }
}

// Final fused kernel: per (batch, 32 t1 rows):
//   k = sum of 4 split-K partials + bias (reduced here, deterministic)
//   logits[t1,t2] = -5e-4 * (|q|^2 + |k|^2 - 2 q.k)
//   out = logits - logsumexp_t2(logits) + log(prior + 1e-8)
__global__ __launch_bounds__(256)
void attn_final(const float* __restrict__ q, const float* __restrict__ kpart,
                const float* __restrict__ kb, const float* __restrict__ prior,
                float* __restrict__ out)
{
    extern __shared__ float sm[];
    float* ksh  = sm;                 // [80][200]
    float* qsh  = sm + 16000;         // [32][81] transposed, padded
    float* k2sh = qsh + 32 * 81;      // [200]
    float* q2sh = k2sh + 200;         // [32]

    const int b   = blockIdx.y;
    const int t10 = blockIdx.x * 32;
    const int tid = threadIdx.x;

    const float* p0 = kpart + 0 * (NB * 16000) + b * 16000;
    const float* p1 = kpart + 1 * (NB * 16000) + b * 16000;
    const float* p2 = kpart + 2 * (NB * 16000) + b * 16000;
    const float* p3 = kpart + 3 * (NB * 16000) + b * 16000;

    for (int i = tid; i < 80 * 200; i += 256) {
        int c = i / 200;
        ksh[i] = (p0[i] + p1[i]) + (p2[i] + p3[i]) + kb[c];
    }
    for (int i = tid; i < 80 * 32; i += 256) {
        int c = i >> 5, tl = i & 31;
        qsh[tl * 81 + c] = q[(b * 80 + c) * 800 + t10 + tl];
    }
    __syncthreads();

    if (tid < 200) {
        float s = 0.f;
#pragma unroll
        for (int c = 0; c < 80; c++) { float v = ksh[c * 200 + tid]; s += v * v; }
        k2sh[tid] = s;
    }
    if (tid < 32) {
        float s = 0.f;
#pragma unroll
        for (int c = 0; c < 80; c++) { float v = qsh[tid * 81 + c]; s += v * v; }
        q2sh[tid] = s;
    }
    __syncthreads();

    const int r0 = (tid >> 4) * 2;   // two t1 rows per thread
    const int cg = tid & 15;

    float acc0[13], acc1[13];
#pragma unroll
    for (int j = 0; j < 13; j++) { acc0[j] = 0.f; acc1[j] = 0.f; }

#pragma unroll 4
    for (int c = 0; c < 80; c++) {
        float q0 = qsh[r0 * 81 + c];
        float q1 = qsh[(r0 + 1) * 81 + c];
#pragma unroll
        for (int j = 0; j < 13; j++) {
            // j==12, cg>=8 reads stale in-bounds smem; result discarded below.
            float kv = ksh[c * 200 + cg + 16 * j];
            acc0[j] += q0 * kv;
            acc1[j] += q1 * kv;
        }
    }

    float q20 = q2sh[r0], q21 = q2sh[r0 + 1];
    float mx0 = -1e30f, mx1 = -1e30f;
#pragma unroll
    for (int j = 0; j < 13; j++) {
        int t2 = cg + 16 * j;
        if (t2 < 200) {
            acc0[j] = -5e-4f * (q20 + k2sh[t2] - 2.f * acc0[j]);
            acc1[j] = -5e-4f * (q21 + k2sh[t2] - 2.f * acc1[j]);
            mx0 = fmaxf(mx0, acc0[j]);
            mx1 = fmaxf(mx1, acc1[j]);
        }
    }
#pragma unroll
    for (int o = 8; o >= 1; o >>= 1) {
        mx0 = fmaxf(mx0, __shfl_xor_sync(0xFFFFFFFFu, mx0, o, 16));
        mx1 = fmaxf(mx1, __shfl_xor_sync(0xFFFFFFFFu, mx1, o, 16));
    }
    float s0 = 0.f, s1 = 0.f;
#pragma unroll
    for (int j = 0; j < 13; j++) {
        int t2 = cg + 16 * j;
        if (t2 < 200) {
            s0 += __expf(acc0[j] - mx0);
            s1 += __expf(acc1[j] - mx1);
        }
    }
#pragma unroll
    for (int o = 8; o >= 1; o >>= 1) {
        s0 += __shfl_xor_sync(0xFFFFFFFFu, s0, o, 16);
        s1 += __shfl_xor_sync(0xFFFFFFFFu, s1, o, 16);
    }
    float l0 = mx0 + logf(s0);
    float l1 = mx1 + logf(s1);

    int base0 = (b * T1V + t10 + r0) * T2V;
    int base1 = base0 + T2V;
#pragma unroll
    for (int j = 0; j < 13; j++) {
        int t2 = cg + 16 * j;
        if (t2 < 200) {
            out[base0 + t2] = acc0[j] - l0 + logf(prior[base0 + t2] + 1e-8f);
            out[base1 + t2] = acc1[j] - l1 + logf(prior[base1 + t2] + 1e-8f);
        }
    }
}

extern "C" void kernel_launch(void* const* d_in, const int* in_sizes, int n_in,
                              void* d_out, int out_size)
{
    const float* queries = (const float*)d_in[0];   // (16, 80, 800)
    const float* keys    = (const float*)d_in[1];   // (16, 256, 200)
    const float* prior   = (const float*)d_in[2];   // (16, 800, 200)
    const float* kw1 = (const float*)d_in[3];       // (512, 256, 3)
    const float* kb1 = (const float*)d_in[4];
    const float* kw2 = (const float*)d_in[5];       // (80, 512, 1)
    const float* kb2 = (const float*)d_in[6];
    const float* qw1 = (const float*)d_in[7];       // (160, 80, 3)
    const float* qb1 = (const float*)d_in[8];
    const float* qw2 = (const float*)d_in[9];       // (80, 160, 1)
    const float* qb2 = (const float*)d_in[10];
    const float* qw3 = (const float*)d_in[11];      // (80, 80, 1)
    const float* qb3 = (const float*)d_in[12];
    float* out = (float*)d_out;

    float *p_kh, *p_kpart, *p_qh1, *p_qh2, *p_q;
    cudaGetSymbolAddress((void**)&p_kh,    g_kh);
    cudaGetSymbolAddress((void**)&p_kpart, g_kpart);
    cudaGetSymbolAddress((void**)&p_qh1,   g_qh1);
    cudaGetSymbolAddress((void**)&p_qh2,   g_qh2);
    cudaGetSymbolAddress((void**)&p_q,     g_q);

    // Key encoder
    //   conv(256->512,k3,p1)+relu : M=512 (BM=64, y=8), N=3200 (BN=128, x=25) -> 200 CTAs
    conv_gemm<256, 512, 3, 1, true,  false, 4, 4, 200, 768><<<dim3(25, 8), 256>>>(kw1, kb1, keys, p_kh);
    //   conv(512->80,k1) split-K 4: BM=80, BN=64 (x=50), z=4 -> 200 CTAs, partials
    conv_gemm<512,  80, 1, 0, false, true,  5, 2, 200, 128><<<dim3(50, 1, 4), 256>>>(kw2, nullptr, p_kh, p_kpart);

    // Query encoder
    //   conv(80->160,k3,p1)+relu : BM=80 (y=2), BN=128 (x=100) -> 200 CTAs
    conv_gemm< 80, 160, 3, 1, true,  false, 5, 4, 800, 240><<<dim3(100, 2), 256>>>(qw1, qb1, queries, p_qh1);
    //   conv(160->80)+relu : BM=80, BN=64 (x=200) -> 200 CTAs
    conv_gemm<160,  80, 1, 0, true,  false, 5, 2, 800, 160><<<dim3(200, 1), 256>>>(qw2, qb2, p_qh1, p_qh2);
    //   conv(80->80) : 200 CTAs
    conv_gemm< 80,  80, 1, 0, false, false, 5, 2, 800,  80><<<dim3(200, 1), 256>>>(qw3, qb3, p_qh2, p_q);

    // Fused split-K reduce + distance + log-softmax + prior
    const int smem = (16000 + 32 * 81 + 200 + 32) * (int)sizeof(float);  // 75296 B
    cudaFuncSetAttribute(attn_final, cudaFuncAttributeMaxDynamicSharedMemorySize, smem);
    attn_final<<<dim3(25, 16), 256, smem>>>(p_q, p_kpart, kb2, prior, out);
}

// round 4
// speedup vs baseline: 1.2897x; 1.2897x over previous
#include <cuda_runtime.h>
#include <math.h>

#define NB 16
#define T1V 800
#define T2V 200

typedef unsigned long long ull;

// One consistent dynamic-smem declaration for all kernels in this TU.
extern __shared__ char smem_dyn[];

// Intermediates (no allocation allowed -> __device__ globals)
__device__ float g_kh   [NB*512*200];     // key conv1 output (post-relu)
__device__ float g_kpart[4*NB*80*200];    // key conv2 split-K partials (no bias)
__device__ float g_qh1  [NB*160*800];     // query conv1 output (post-relu)
__device__ float g_qh2  [NB*80*800];      // query conv2 output (post-relu)
__device__ float g_q    [NB*80*800];      // query encoder output

// Packed dual-FMA (sm_103a): d.lo += a.lo*b.lo ; d.hi += a.hi*b.hi
#define FFMA2(d, a, b) asm("fma.rn.f32x2 %0, %1, %2, %0;" : "+l"(d) : "l"(a), "l"(b))
#define UNPACK2(lo, hi, p) asm("mov.b64 {%0, %1}, %2;" : "=f"(lo), "=f"(hi) : "l"(p))

// Implicit-im2col conv-as-GEMM body, f32x2-packed on N, double-buffered smem.
//   Y[b, m, t] = bias[m] + sum_{cin,kk} W[m, cin, kk] * X[b, cin, t+kk-PAD]
// GEMM: M = COUT, N = NB*T, K = CIN*KW (kappa = kk*CIN + cin).
// 256 threads as 16(tx) x 16(ty). BM=16*TM, BN=32*TNP, BK=16.
// A stored in smem pre-duplicated (float2{w,w}) -> inner loop is LDS + FFMA2 only.
// SPLITK: kz selects K-chunk [kz*KTOT, (kz+1)*KTOT); output to partial buffer kz.
template<int CIN, int COUT, int KW, int PAD, bool RELU, bool SPLITK,
         int TM, int TNP, int T, int KTOT>
__device__ __forceinline__
void conv_body(const float* __restrict__ W, const float* __restrict__ bias,
               const float* __restrict__ X, float* __restrict__ Y,
               int bx, int by, int kz, char* smem_raw)
{
    constexpr int BM = 16 * TM, BN = 32 * TNP, BK = 16;
    constexpr int KFULL = CIN * KW;
    constexpr int LA = (BK * BM) / 256;
    constexpr int LB = (BK * BN) / 256;
    constexpr int NK = KTOT / BK;

    float2 (*As2)[BK][BM] = reinterpret_cast<float2 (*)[BK][BM]>(smem_raw);
    float  (*Bs )[BK][BN] = reinterpret_cast<float  (*)[BK][BN]>(smem_raw + 2 * BK * BM * 8);

    const int tid = threadIdx.x;
    const int tx  = tid & 15, ty = tid >> 4;
    const int n0  = bx * BN;
    const int m0  = by * BM;
    const int kbase = SPLITK ? kz * KTOT : 0;

    // Per-thread B column decode (loop-invariant pieces).
    int b_t[LB], b_row[LB];
#pragma unroll
    for (int s = 0; s < LB; s++) {
        int i  = tid + s * 256;
        int gn = n0 + (i & (BN - 1));
        int bb = gn / T;
        b_t[s]   = gn - bb * T;
        b_row[s] = bb * CIN * T;
    }

    ull acc[TM][TNP];
#pragma unroll
    for (int i = 0; i < TM; i++)
#pragma unroll
        for (int j = 0; j < TNP; j++) acc[i][j] = 0ull;

    float aR[LA], bR[LB];

    // ---- prologue: load K-tile 0 ----
#pragma unroll
    for (int s = 0; s < LA; s++) {
        int i   = tid + s * 256;
        int kap = kbase + (i & (BK - 1));
        int m   = m0 + (i >> 4);
        if (KW == 1) {
            aR[s] = W[m * KFULL + kap];
        } else {
            int kk = kap / CIN, cin = kap - kk * CIN;
            aR[s] = W[m * KFULL + cin * KW + kk];
        }
    }
#pragma unroll
    for (int s = 0; s < LB; s++) {
        int i   = tid + s * 256;
        int kap = kbase + i / BN;
        if (KW == 1) {
            bR[s] = X[b_row[s] + kap * T + b_t[s]];
        } else {
            int kk = kap / CIN, cin = kap - kk * CIN;
            int tin = b_t[s] + kk - PAD;
            float v = 0.f;
            if ((unsigned)tin < (unsigned)T) v = X[b_row[s] + cin * T + tin];
            bR[s] = v;
        }
    }
#pragma unroll
    for (int s = 0; s < LA; s++) {
        int i = tid + s * 256;
        As2[0][i & (BK - 1)][i >> 4] = make_float2(aR[s], aR[s]);
    }
#pragma unroll
    for (int s = 0; s < LB; s++) {
        int i = tid + s * 256;
        Bs[0][i / BN][i & (BN - 1)] = bR[s];
    }
    __syncthreads();

    int buf = 0;
    for (int kt = 0; kt < NK; kt++) {
        // prefetch next tile into registers (overlaps compute)
        if (kt + 1 < NK) {
            const int k0 = (kt + 1) * BK;
#pragma unroll
            for (int s = 0; s < LA; s++) {
                int i   = tid + s * 256;
                int kap = kbase + k0 + (i & (BK - 1));
                int m   = m0 + (i >> 4);
                if (KW == 1) {
                    aR[s] = W[m * KFULL + kap];
                } else {
                    int kk = kap / CIN, cin = kap - kk * CIN;
                    aR[s] = W[m * KFULL + cin * KW + kk];
                }
            }
#pragma unroll
            for (int s = 0; s < LB; s++) {
                int i   = tid + s * 256;
                int kap = kbase + k0 + i / BN;
                if (KW == 1) {
                    bR[s] = X[b_row[s] + kap * T + b_t[s]];
                } else {
                    int kk = kap / CIN, cin = kap - kk * CIN;
                    int tin = b_t[s] + kk - PAD;
                    float v = 0.f;
                    if ((unsigned)tin < (unsigned)T) v = X[b_row[s] + cin * T + tin];
                    bR[s] = v;
                }
            }
        }

        // compute current tile: pure LDS + FFMA2
#pragma unroll
        for (int kl = 0; kl < BK; kl++) {
            const ull* Ap = reinterpret_cast<const ull*>(&As2[buf][kl][ty * TM]);
            const ull* Bp = reinterpret_cast<const ull*>(&Bs[buf][kl][tx * TNP * 2]);
            ull a[TM], b[TNP];
#pragma unroll
            for (int i = 0; i < TM; i++) a[i] = Ap[i];
#pragma unroll
            for (int j = 0; j < TNP; j++) b[j] = Bp[j];
#pragma unroll
            for (int i = 0; i < TM; i++)
#pragma unroll
                for (int j = 0; j < TNP; j++)
                    FFMA2(acc[i][j], a[i], b[j]);
        }

        if (kt + 1 < NK) {
#pragma unroll
            for (int s = 0; s < LA; s++) {
                int i = tid + s * 256;
                As2[buf ^ 1][i & (BK - 1)][i >> 4] = make_float2(aR[s], aR[s]);
            }
#pragma unroll
            for (int s = 0; s < LB; s++) {
                int i = tid + s * 256;
                Bs[buf ^ 1][i / BN][i & (BN - 1)] = bR[s];
            }
            __syncthreads();
        }
        buf ^= 1;
    }

    // ---- epilogue ----
    float* Yp = SPLITK ? Y + kz * (COUT * NB * T) : Y;
#pragma unroll
    for (int j = 0; j < TNP; j++) {
        float lo[TM], hi[TM];
#pragma unroll
        for (int i = 0; i < TM; i++) UNPACK2(lo[i], hi[i], acc[i][j]);

        int gn0 = n0 + tx * TNP * 2 + 2 * j;
#pragma unroll
        for (int h = 0; h < 2; h++) {
            int gn = gn0 + h;
            int bb = gn / T;
            int tt = gn - bb * T;
#pragma unroll
            for (int i = 0; i < TM; i++) {
                int m = m0 + ty * TM + i;
                float v = (h ? hi[i] : lo[i]);
                if (!SPLITK) {
                    v += bias[m];
                    if (RELU) v = fmaxf(v, 0.f);
                }
                Yp[(bb * COUT + m) * T + tt] = v;
            }
        }
    }
}

// Launch A: z=0 -> key conv1 (256->512,k3)+relu [200 CTAs]
//           z=1 -> query conv1 (80->160,k3)+relu [200 CTAs]
__global__ __launch_bounds__(256, 2)
void fusedA(const float* __restrict__ kw1, const float* __restrict__ kb1,
            const float* __restrict__ keys, float* __restrict__ kh,
            const float* __restrict__ qw1, const float* __restrict__ qb1,
            const float* __restrict__ queries, float* __restrict__ qh1)
{
    int bid = blockIdx.x;
    if (blockIdx.z == 0) {
        // k1: BM=64 (TM=4), BN=128 (TNP=4), grid 25 x 8
        conv_body<256, 512, 3, 1, true, false, 4, 4, 200, 768>(
            kw1, kb1, keys, kh, bid % 25, bid / 25, 0, smem_dyn);
    } else {
        // q1: BM=80 (TM=5), BN=128 (TNP=4), grid 100 x 2
        conv_body<80, 160, 3, 1, true, false, 5, 4, 800, 240>(
            qw1, qb1, queries, qh1, bid % 100, bid / 100, 0, smem_dyn);
    }
}

// Launch B: z=0 -> key conv2 (512->80,k1) split-K4 [200 CTAs, partials]
//           z=1 -> query conv2 (160->80,k1)+relu [200 CTAs]
__global__ __launch_bounds__(256, 2)
void fusedB(const float* __restrict__ kw2, const float* __restrict__ kh,
            float* __restrict__ kpart,
            const float* __restrict__ qw2, const float* __restrict__ qb2,
            const float* __restrict__ qh1, float* __restrict__ qh2)
{
    int bid = blockIdx.x;
    if (blockIdx.z == 0) {
        // k2: BM=80 (TM=5), BN=64 (TNP=2), grid 50, K-chunks 4x128
        conv_body<512, 80, 1, 0, false, true, 5, 2, 200, 128>(
            kw2, nullptr, kh, kpart, bid % 50, 0, bid / 50, smem_dyn);
    } else {
        // q2: BM=80 (TM=5), BN=64 (TNP=2), grid 200
        conv_body<160, 80, 1, 0, true, false, 5, 2, 800, 160>(
            qw2, qb2, qh1, qh2, bid, 0, 0, smem_dyn);
    }
}

// Launch C: query conv3 (80->80,k1) [200 CTAs]
__global__ __launch_bounds__(256, 2)
void convC(const float* __restrict__ qw3, const float* __restrict__ qb3,
           const float* __restrict__ qh2, float* __restrict__ q)
{
    conv_body<80, 80, 1, 0, false, false, 5, 2, 800, 80>(
        qw3, qb3, qh2, q, blockIdx.x, 0, 0, smem_dyn);
}

// Final fused kernel: per (batch, 32 t1 rows):
//   k = sum of 4 split-K partials + bias (deterministic reduce)
//   logits = -5e-4 * (|q|^2 + |k|^2 - 2 q.k)
//   out = logits - logsumexp_t2(logits) + log(prior + 1e-8)
__global__ __launch_bounds__(256)
void attn_final(const float* __restrict__ q, const float* __restrict__ kpart,
                const float* __restrict__ kb, const float* __restrict__ prior,
                float* __restrict__ out)
{
    float* sm   = reinterpret_cast<float*>(smem_dyn);
    float* ksh  = sm;                 // [80][200]
    float* qsh  = sm + 16000;         // [32][81] transposed, padded
    float* k2sh = qsh + 32 * 81;      // [200]
    float* q2sh = k2sh + 200;         // [32]

    const int b   = blockIdx.y;
    const int t10 = blockIdx.x * 32;
    const int tid = threadIdx.x;

    const float* p0 = kpart + 0 * (NB * 16000) + b * 16000;
    const float* p1 = kpart + 1 * (NB * 16000) + b * 16000;
    const float* p2 = kpart + 2 * (NB * 16000) + b * 16000;
    const float* p3 = kpart + 3 * (NB * 16000) + b * 16000;

    for (int i = tid; i < 80 * 200; i += 256) {
        int c = i / 200;
        ksh[i] = (p0[i] + p1[i]) + (p2[i] + p3[i]) + kb[c];
    }
    for (int i = tid; i < 80 * 32; i += 256) {
        int c = i >> 5, tl = i & 31;
        qsh[tl * 81 + c] = q[(b * 80 + c) * 800 + t10 + tl];
    }
    __syncthreads();

    if (tid < 200) {
        float s = 0.f;
#pragma unroll
        for (int c = 0; c < 80; c++) { float v = ksh[c * 200 + tid]; s += v * v; }
        k2sh[tid] = s;
    }
    if (tid < 32) {
        float s = 0.f;
#pragma unroll
        for (int c = 0; c < 80; c++) { float v = qsh[tid * 81 + c]; s += v * v; }
        q2sh[tid] = s;
    }
    __syncthreads();

    const int r0 = (tid >> 4) * 2;   // two t1 rows per thread
    const int cg = tid & 15;

    float acc0[13], acc1[13];
#pragma unroll
    for (int j = 0; j < 13; j++) { acc0[j] = 0.f; acc1[j] = 0.f; }

#pragma unroll 4
    for (int c = 0; c < 80; c++) {
        float q0 = qsh[r0 * 81 + c];
        float q1 = qsh[(r0 + 1) * 81 + c];
#pragma unroll
        for (int j = 0; j < 13; j++) {
            // j==12, cg>=8 reads stale in-bounds smem; result discarded below.
            float kv = ksh[c * 200 + cg + 16 * j];
            acc0[j] += q0 * kv;
            acc1[j] += q1 * kv;
        }
    }

    float q20 = q2sh[r0], q21 = q2sh[r0 + 1];
    float mx0 = -1e30f, mx1 = -1e30f;
#pragma unroll
    for (int j = 0; j < 13; j++) {
        int t2 = cg + 16 * j;
        if (t2 < 200) {
            acc0[j] = -5e-4f * (q20 + k2sh[t2] - 2.f * acc0[j]);
            acc1[j] = -5e-4f * (q21 + k2sh[t2] - 2.f * acc1[j]);
            mx0 = fmaxf(mx0, acc0[j]);
            mx1 = fmaxf(mx1, acc1[j]);
        }
    }
#pragma unroll
    for (int o = 8; o >= 1; o >>= 1) {
        mx0 = fmaxf(mx0, __shfl_xor_sync(0xFFFFFFFFu, mx0, o, 16));
        mx1 = fmaxf(mx1, __shfl_xor_sync(0xFFFFFFFFu, mx1, o, 16));
    }
    float s0 = 0.f, s1 = 0.f;
#pragma unroll
    for (int j = 0; j < 13; j++) {
        int t2 = cg + 16 * j;
        if (t2 < 200) {
            s0 += __expf(acc0[j] - mx0);
            s1 += __expf(acc1[j] - mx1);
        }
    }
#pragma unroll
    for (int o = 8; o >= 1; o >>= 1) {
        s0 += __shfl_xor_sync(0xFFFFFFFFu, s0, o, 16);
        s1 += __shfl_xor_sync(0xFFFFFFFFu, s1, o, 16);
    }
    float l0 = mx0 + logf(s0);
    float l1 = mx1 + logf(s1);

    int base0 = (b * T1V + t10 + r0) * T2V;
    int base1 = base0 + T2V;
#pragma unroll
    for (int j = 0; j < 13; j++) {
        int t2 = cg + 16 * j;
        if (t2 < 200) {
            out[base0 + t2] = acc0[j] - l0 + logf(prior[base0 + t2] + 1e-8f);
            out[base1 + t2] = acc1[j] - l1 + logf(prior[base1 + t2] + 1e-8f);
        }
    }
}

extern "C" void kernel_launch(void* const* d_in, const int* in_sizes, int n_in,
                              void* d_out, int out_size)
{
    const float* queries = (const float*)d_in[0];   // (16, 80, 800)
    const float* keys    = (const float*)d_in[1];   // (16, 256, 200)
    const float* prior   = (const float*)d_in[2];   // (16, 800, 200)
    const float* kw1 = (const float*)d_in[3];       // (512, 256, 3)
    const float* kb1 = (const float*)d_in[4];
    const float* kw2 = (const float*)d_in[5];       // (80, 512, 1)
    const float* kb2 = (const float*)d_in[6];
    const float* qw1 = (const float*)d_in[7];       // (160, 80, 3)
    const float* qb1 = (const float*)d_in[8];
    const float* qw2 = (const float*)d_in[9];       // (80, 160, 1)
    const float* qb2 = (const float*)d_in[10];
    const float* qw3 = (const float*)d_in[11];      // (80, 80, 1)
    const float* qb3 = (const float*)d_in[12];
    float* out = (float*)d_out;

    float *p_kh, *p_kpart, *p_qh1, *p_qh2, *p_q;
    cudaGetSymbolAddress((void**)&p_kh,    g_kh);
    cudaGetSymbolAddress((void**)&p_kpart, g_kpart);
    cudaGetSymbolAddress((void**)&p_qh1,   g_qh1);
    cudaGetSymbolAddress((void**)&p_qh2,   g_qh2);
    cudaGetSymbolAddress((void**)&p_q,     g_q);

    // smem: 2*16*BM*8 (A, float2) + 2*16*BN*4 (B)
    const int smemA = 2*16*80*8 + 2*16*128*4;   // q1 shape is max: 36864
    const int smemB = 2*16*80*8 + 2*16*64*4;    // 28672
    const int smemC = smemB;

    // Launch A: k1 + q1 together (400 CTAs)
    fusedA<<<dim3(200, 1, 2), 256, smemA>>>(kw1, kb1, keys, p_kh,
                                            qw1, qb1, queries, p_qh1);
    // Launch B: k2 (split-K4) + q2 together (400 CTAs)
    fusedB<<<dim3(200, 1, 2), 256, smemB>>>(kw2, p_kh, p_kpart,
                                            qw2, qb2, p_qh1, p_qh2);
    // Launch C: q3 (200 CTAs)
    convC<<<dim3(200, 1, 1), 256, smemC>>>(qw3, qb3, p_qh2, p_q);

    // Fused split-K reduce + distance + log-softmax + prior (400 CTAs)
    const int smemF = (16000 + 32 * 81 + 200 + 32) * (int)sizeof(float);  // 75296 B
    cudaFuncSetAttribute(attn_final, cudaFuncAttributeMaxDynamicSharedMemorySize, smemF);
    attn_final<<<dim3(25, 16), 256, smemF>>>(p_q, p_kpart, kb2, prior, out);
}

// round 6
// speedup vs baseline: 3.3256x; 2.5786x over previous
#include <cuda_runtime.h>
#include <cuda_bf16.h>
#include <math.h>
#include <stdint.h>

#define NB 16
#define T1V 800
#define T2V 200

extern __shared__ char smem_dyn[];

// Intermediates (no allocation allowed -> __device__ globals)
__device__ float g_kh [NB*512*200];   // key conv1 out (post-relu)
__device__ float g_k  [NB*80*200];    // key encoder out
__device__ float g_qh1[NB*160*800];   // query conv1 out (post-relu)
__device__ float g_qh2[NB*80*800];    // query conv2 out (post-relu)
__device__ float g_q  [NB*80*800];    // query encoder out

// Pre-transposed, zero-padded bf16 weights: Wt[kap][m], kap = kk*CIN + cin, Kpad = NC*32
__device__ __nv_bfloat16 g_wt1 [768*512];
__device__ __nv_bfloat16 g_wt2 [512*80];
__device__ __nv_bfloat16 g_wtq1[256*160];
__device__ __nv_bfloat16 g_wtq2[160*80];
__device__ __nv_bfloat16 g_wtq3[ 96*80];

// ---------------- mma/ldmatrix helpers (baseline PTX, works on sm_103) ----------------
__device__ __forceinline__ uint32_t smem_u32(const void* p) {
    uint32_t a;
    asm("{ .reg .u64 t; cvta.to.shared.u64 t, %1; cvt.u32.u64 %0, t; }" : "=r"(a) : "l"(p));
    return a;
}
__device__ __forceinline__ void ldsm4t(uint32_t r[4], uint32_t addr) {
    asm volatile("ldmatrix.sync.aligned.m8n8.x4.trans.shared.b16 {%0,%1,%2,%3}, [%4];"
                 : "=r"(r[0]), "=r"(r[1]), "=r"(r[2]), "=r"(r[3]) : "r"(addr));
}
__device__ __forceinline__ void mma16816(float c[4], const uint32_t a[4],
                                         uint32_t b0, uint32_t b1) {
    asm volatile("mma.sync.aligned.m16n8k16.row.col.f32.bf16.bf16.f32 "
                 "{%0,%1,%2,%3}, {%4,%5,%6,%7}, {%8,%9}, {%0,%1,%2,%3};"
                 : "+f"(c[0]), "+f"(c[1]), "+f"(c[2]), "+f"(c[3])
                 : "r"(a[0]), "r"(a[1]), "r"(a[2]), "r"(a[3]), "r"(b0), "r"(b1));
}

// ---------------- weight prep: W[m][cin][kk] (fp32) -> Wt[kap][m] (bf16, K zero-padded) ----------------
__device__ __forceinline__ void wt_fill(__nv_bfloat16* dst, const float* W,
                                        int idx, int COUT, int CIN, int KW, int K) {
    int kap = idx / COUT, m = idx - kap * COUT;
    float v = 0.f;
    if (kap < K) {
        int kk = kap / CIN, cin = kap - kk * CIN;
        v = W[m * K + cin * KW + kk];
    }
    dst[idx] = __float2bfloat16(v);
}

__global__ __launch_bounds__(256)
void prep_weights(const float* kw1, const float* kw2, const float* qw1,
                  const float* qw2, const float* qw3) {
    const int s1 = 768*512, s2 = 512*80, s3 = 256*160, s4 = 160*80, s5 = 96*80;
    int idx = blockIdx.x * 256 + threadIdx.x;
    if (idx < s1) { wt_fill(g_wt1, kw1, idx, 512, 256, 3, 768); return; }
    idx -= s1;
    if (idx < s2) { wt_fill(g_wt2, kw2, idx, 80, 512, 1, 512); return; }
    idx -= s2;
    if (idx < s3) { wt_fill(g_wtq1, qw1, idx, 160, 80, 3, 240); return; }
    idx -= s3;
    if (idx < s4) { wt_fill(g_wtq2, qw2, idx, 80, 160, 1, 160); return; }
    idx -= s4;
    if (idx < s5) { wt_fill(g_wtq3, qw3, idx, 80, 80, 1, 80); return; }
}

// ---------------- conv-as-GEMM via warp-level bf16 mma.sync ----------------
// D[m, n] = sum_kap Wt[kap][m] * B[n][kap],  B = im2col(X)^T, n = bb*T + t.
// Smem: A[k(32)][BMp] and B[k(32)][BNp] bf16 (k-major both), fragments via ldmatrix.x4.trans.
// 256 threads = 8 warps, warp grid WY x WX; warp tile (TM16*16) x (TN8*8); BK=32 double-buffered.
template<int CIN, int COUT, int KW, int PAD, bool RELU, int T,
         int WY, int WX, int TM16, int TN8, int NC>
__device__ __forceinline__
void mma_conv(const __nv_bfloat16* __restrict__ Wt, const float* __restrict__ bias,
              const float* __restrict__ X, float* __restrict__ Y,
              int mtile, int ntile)
{
    constexpr int BM = WY * TM16 * 16;
    constexpr int BN = WX * TN8 * 8;     static_assert(BN == 128, "BN must be 128");
    constexpr int K   = CIN * KW;
    constexpr int BMp = BM + 8;          // bf16 row stride (16B-aligned, conflict-free)
    constexpr int BNp = 136;
    constexpr int AWW = BM / 2;          // A 32-bit words per k-row
    constexpr int LAW = 32 * AWW / 256;  // A words per thread
    constexpr int LBW = 8;               // B words per thread (32*64/256)
    constexpr int ABYTES = 32 * BMp * 2;
    constexpr int BBYTES = 32 * BNp * 2;

    const int tid = threadIdx.x;
    const int wid = tid >> 5, lid = tid & 31;
    const int wy = wid / WX, wx = wid - wy * WX;
    const int wm0 = wy * TM16 * 16, wn0 = wx * TN8 * 8;

    uint32_t* A32[2] = { reinterpret_cast<uint32_t*>(smem_dyn),
                         reinterpret_cast<uint32_t*>(smem_dyn + ABYTES) };
    uint32_t* B32[2] = { reinterpret_cast<uint32_t*>(smem_dyn + 2*ABYTES),
                         reinterpret_cast<uint32_t*>(smem_dyn + 2*ABYTES + BBYTES) };
    const uint32_t uS = smem_u32(smem_dyn);
    const uint32_t uA[2] = { uS, uS + ABYTES };
    const uint32_t uB[2] = { uS + 2*ABYTES, uS + 2*ABYTES + BBYTES };

    // ldmatrix per-lane offsets (bytes), trans layout [k][cols]:
    const int g = lid >> 3, lr = lid & 7;
    const uint32_t a_off = ((lr + ((g & 2) ? 8 : 0)) * BMp + ((g & 1) ? 8 : 0)) * 2;
    const uint32_t b_off = ((lr + ((g & 1) ? 8 : 0)) * BNp + ((g & 2) ? 8 : 0)) * 2;

    float acc[TM16][TN8][4];
#pragma unroll
    for (int i = 0; i < TM16; i++)
#pragma unroll
        for (int j = 0; j < TN8; j++)
#pragma unroll
            for (int r = 0; r < 4; r++) acc[i][j][r] = 0.f;

    const uint32_t* Wt32 = reinterpret_cast<const uint32_t*>(Wt);
    const int awbase = mtile * BM / 2;

    uint32_t ra[LAW], rb[LBW];

    auto loadA = [&](int kc) {
#pragma unroll
        for (int s = 0; s < LAW; s++) {
            int w = tid + s * 256;
            int mp = w % AWW, k = w / AWW;
            ra[s] = Wt32[(size_t)(kc * 32 + k) * (COUT / 2) + awbase + mp];
        }
    };
    auto loadB = [&](int kc) {
#pragma unroll
        for (int s = 0; s < LBW; s++) {
            int w = tid + s * 256;
            int np = w & 63, k = w >> 6;
            int kap = kc * 32 + k;
            int n = ntile * 128 + 2 * np;
            int bb = n / T, t = n - bb * T;
            float v0 = 0.f, v1 = 0.f;
            if (kap < K) {
                if (KW == 1) {
                    const float* xr = X + (size_t)(bb * CIN + kap) * T + t;
                    v0 = xr[0]; v1 = xr[1];
                } else {
                    int kk = kap / CIN, cin = kap - kk * CIN;
                    int tin = t + kk - PAD;
                    const float* xr = X + (size_t)(bb * CIN + cin) * T;
                    if ((unsigned)tin < (unsigned)T)       v0 = xr[tin];
                    if ((unsigned)(tin + 1) < (unsigned)T) v1 = xr[tin + 1];
                }
            }
            __nv_bfloat162 h = __floats2bfloat162_rn(v0, v1);
            rb[s] = *reinterpret_cast<uint32_t*>(&h);
        }
    };
    auto stsA = [&](int p) {
#pragma unroll
        for (int s = 0; s < LAW; s++) {
            int w = tid + s * 256;
            int mp = w % AWW, k = w / AWW;
            A32[p][k * (BMp / 2) + mp] = ra[s];
        }
    };
    auto stsB = [&](int p) {
#pragma unroll
        for (int s = 0; s < LBW; s++) {
            int w = tid + s * 256;
            int np = w & 63, k = w >> 6;
            B32[p][k * (BNp / 2) + np] = rb[s];
        }
    };
    auto compute = [&](int p) {
#pragma unroll
        for (int ks = 0; ks < 32; ks += 16) {
            uint32_t af[TM16][4];
#pragma unroll
            for (int i = 0; i < TM16; i++)
                ldsm4t(af[i], uA[p] + a_off + (ks * BMp + wm0 + 16 * i) * 2);
            uint32_t bf[TN8 / 2][4];
#pragma unroll
            for (int jj = 0; jj < TN8 / 2; jj++)
                ldsm4t(bf[jj], uB[p] + b_off + (ks * BNp + wn0 + 16 * jj) * 2);
#pragma unroll
            for (int i = 0; i < TM16; i++)
#pragma unroll
                for (int j = 0; j < TN8; j++)
                    mma16816(acc[i][j], af[i], bf[j >> 1][(j & 1) * 2], bf[j >> 1][(j & 1) * 2 + 1]);
        }
    };

    // prologue
    loadA(0); loadB(0);
    stsA(0);  stsB(0);
    __syncthreads();

    for (int kc = 0; kc < NC; kc++) {
        int p = kc & 1;
        if (kc + 1 < NC) { loadA(kc + 1); loadB(kc + 1); }
        compute(p);
        if (kc + 1 < NC) { stsA(p ^ 1); stsB(p ^ 1); __syncthreads(); }
    }

    // epilogue: direct float2 stores (all tile dims divide exactly -> no predicates)
#pragma unroll
    for (int i = 0; i < TM16; i++) {
        int r0 = mtile * BM + wm0 + 16 * i + (lid >> 2);
        float bv0 = bias[r0], bv1 = bias[r0 + 8];
#pragma unroll
        for (int j = 0; j < TN8; j++) {
            int n = ntile * 128 + wn0 + 8 * j + (lid & 3) * 2;
            int bb = n / T, t = n - bb * T;
            float2 v0, v1;
            v0.x = acc[i][j][0] + bv0; v0.y = acc[i][j][1] + bv0;
            v1.x = acc[i][j][2] + bv1; v1.y = acc[i][j][3] + bv1;
            if (RELU) {
                v0.x = fmaxf(v0.x, 0.f); v0.y = fmaxf(v0.y, 0.f);
                v1.x = fmaxf(v1.x, 0.f); v1.y = fmaxf(v1.y, 0.f);
            }
            *reinterpret_cast<float2*>(&Y[(size_t)(bb * COUT + r0) * T + t])     = v0;
            *reinterpret_cast<float2*>(&Y[(size_t)(bb * COUT + r0 + 8) * T + t]) = v1;
        }
    }
}

// Launch A: z=0 -> key conv1 (256->512,k3)+relu [100 CTAs], z=1 -> query conv1 (80->160,k3)+relu [200 CTAs]
__global__ __launch_bounds__(256)
void fusedA(const float* __restrict__ kb1, const float* __restrict__ keys, float* __restrict__ kh,
            const float* __restrict__ qb1, const float* __restrict__ queries, float* __restrict__ qh1)
{
    int bx = blockIdx.x;
    if (blockIdx.z == 0) {
        if (bx >= 100) return;
        mma_conv<256, 512, 3, 1, true, 200, 2, 4, 4, 4, 24>(g_wt1, kb1, keys, kh, bx / 25, bx % 25);
    } else {
        mma_conv<80, 160, 3, 1, true, 800, 1, 8, 5, 2, 8>(g_wtq1, qb1, queries, qh1, bx / 100, bx % 100);
    }
}

// Launch B: z=0 -> key conv2 (512->80,k1) [25 CTAs], z=1 -> query conv2 (160->80,k1)+relu [100 CTAs]
__global__ __launch_bounds__(256)
void fusedB(const float* __restrict__ kb2, const float* __restrict__ kh, float* __restrict__ kout,
            const float* __restrict__ qb2, const float* __restrict__ qh1, float* __restrict__ qh2)
{
    int bx = blockIdx.x;
    if (blockIdx.z == 0) {
        if (bx >= 25) return;
        mma_conv<512, 80, 1, 0, false, 200, 1, 8, 5, 2, 16>(g_wt2, kb2, kh, kout, 0, bx);
    } else {
        mma_conv<160, 80, 1, 0, true, 800, 1, 8, 5, 2, 5>(g_wtq2, qb2, qh1, qh2, 0, bx);
    }
}

// Launch C: query conv3 (80->80,k1) [100 CTAs]
__global__ __launch_bounds__(256)
void convC(const float* __restrict__ qb3, const float* __restrict__ qh2, float* __restrict__ q)
{
    mma_conv<80, 80, 1, 0, false, 800, 1, 8, 5, 2, 3>(g_wtq3, qb3, qh2, q, 0, blockIdx.x);
}

// ---------------- final attention (MUFU-roofline-bound, unchanged math) ----------------
__global__ __launch_bounds__(256)
void attn_final(const float* __restrict__ q, const float* __restrict__ k,
                const float* __restrict__ prior, float* __restrict__ out)
{
    float* sm   = reinterpret_cast<float*>(smem_dyn);
    float* ksh  = sm;                 // [80][200]
    float* qsh  = sm + 16000;         // [32][81] transposed, padded
    float* k2sh = qsh + 32 * 81;      // [200]
    float* q2sh = k2sh + 200;         // [32]

    const int b   = blockIdx.y;
    const int t10 = blockIdx.x * 32;
    const int tid = threadIdx.x;

    for (int i = tid; i < 80 * 200; i += 256)
        ksh[i] = k[b * 16000 + i];
    for (int i = tid; i < 80 * 32; i += 256) {
        int c = i >> 5, tl = i & 31;
        qsh[tl * 81 + c] = q[(b * 80 + c) * 800 + t10 + tl];
    }
    __syncthreads();

    if (tid < 200) {
        float s = 0.f;
#pragma unroll
        for (int c = 0; c < 80; c++) { float v = ksh[c * 200 + tid]; s += v * v; }
        k2sh[tid] = s;
    }
    if (tid < 32) {
        float s = 0.f;
#pragma unroll
        for (int c = 0; c < 80; c++) { float v = qsh[tid * 81 + c]; s += v * v; }
        q2sh[tid] = s;
    }
    __syncthreads();

    const int r0 = (tid >> 4) * 2;
    const int cg = tid & 15;

    float acc0[13], acc1[13];
#pragma unroll
    for (int j = 0; j < 13; j++) { acc0[j] = 0.f; acc1[j] = 0.f; }

#pragma unroll 4
    for (int c = 0; c < 80; c++) {
        float q0 = qsh[r0 * 81 + c];
        float q1 = qsh[(r0 + 1) * 81 + c];
#pragma unroll
        for (int j = 0; j < 13; j++) {
            // j==12, cg>=8 reads stale in-bounds smem; result discarded below.
            float kv = ksh[c * 200 + cg + 16 * j];
            acc0[j] += q0 * kv;
            acc1[j] += q1 * kv;
        }
    }

    float q20 = q2sh[r0], q21 = q2sh[r0 + 1];
    float mx0 = -1e30f, mx1 = -1e30f;
#pragma unroll
    for (int j = 0; j < 13; j++) {
        int t2 = cg + 16 * j;
        if (t2 < 200) {
            acc0[j] = -5e-4f * (q20 + k2sh[t2] - 2.f * acc0[j]);
            acc1[j] = -5e-4f * (q21 + k2sh[t2] - 2.f * acc1[j]);
            mx0 = fmaxf(mx0, acc0[j]);
            mx1 = fmaxf(mx1, acc1[j]);
        }
    }
#pragma unroll
    for (int o = 8; o >= 1; o >>= 1) {
        mx0 = fmaxf(mx0, __shfl_xor_sync(0xFFFFFFFFu, mx0, o, 16));
        mx1 = fmaxf(mx1, __shfl_xor_sync(0xFFFFFFFFu, mx1, o, 16));
    }
    float s0 = 0.f, s1 = 0.f;
#pragma unroll
    for (int j = 0; j < 13; j++) {
        int t2 = cg + 16 * j;
        if (t2 < 200) {
            s0 += __expf(acc0[j] - mx0);
            s1 += __expf(acc1[j] - mx1);
        }
    }
#pragma unroll
    for (int o = 8; o >= 1; o >>= 1) {
        s0 += __shfl_xor_sync(0xFFFFFFFFu, s0, o, 16);
        s1 += __shfl_xor_sync(0xFFFFFFFFu, s1, o, 16);
    }
    float l0 = mx0 + __logf(s0);
    float l1 = mx1 + __logf(s1);

    int base0 = (b * T1V + t10 + r0) * T2V;
    int base1 = base0 + T2V;
#pragma unroll
    for (int j = 0; j < 13; j++) {
        int t2 = cg + 16 * j;
        if (t2 < 200) {
            out[base0 + t2] = acc0[j] - l0 + __logf(prior[base0 + t2] + 1e-8f);
            out[base1 + t2] = acc1[j] - l1 + __logf(prior[base1 + t2] + 1e-8f);
        }
    }
}

// ---------------- launcher ----------------
extern "C" void kernel_launch(void* const* d_in, const int* in_sizes, int n_in,
                              void* d_out, int out_size)
{
    const float* queries = (const float*)d_in[0];   // (16, 80, 800)
    const float* keys    = (const float*)d_in[1];   // (16, 256, 200)
    const float* prior   = (const float*)d_in[2];   // (16, 800, 200)
    const float* kw1 = (const float*)d_in[3];       // (512, 256, 3)
    const float* kb1 = (const float*)d_in[4];
    const float* kw2 = (const float*)d_in[5];       // (80, 512, 1)
    const float* kb2 = (const float*)d_in[6];
    const float* qw1 = (const float*)d_in[7];       // (160, 80, 3)
    const float* qb1 = (const float*)d_in[8];
    const float* qw2 = (const float*)d_in[9];       // (80, 160, 1)
    const float* qb2 = (const float*)d_in[10];
    const float* qw3 = (const float*)d_in[11];      // (80, 80, 1)
    const float* qb3 = (const float*)d_in[12];
    float* out = (float*)d_out;

    float *p_kh, *p_k, *p_qh1, *p_qh2, *p_q;
    cudaGetSymbolAddress((void**)&p_kh,  g_kh);
    cudaGetSymbolAddress((void**)&p_k,   g_k);
    cudaGetSymbolAddress((void**)&p_qh1, g_qh1);
    cudaGetSymbolAddress((void**)&p_qh2, g_qh2);
    cudaGetSymbolAddress((void**)&p_q,   g_q);

    // 0) weight transpose/convert (one-time per call, ~0.5M elems)
    prep_weights<<<1937, 256>>>(kw1, kw2, qw1, qw2, qw3);

    // smem: 2*A + 2*B. Config A (BM=128): 2*32*136*2*2 = 34816 B. Config B (BM=80): 28672 B.
    const int smemA = 2 * (32 * 136 * 2) + 2 * (32 * 136 * 2);   // 34816
    const int smemB = 2 * (32 * 88 * 2)  + 2 * (32 * 136 * 2);   // 28672

    // 1) k1 (100 CTAs) + q1 (200 CTAs)
    fusedA<<<dim3(200, 1, 2), 256, smemA>>>(kb1, keys, p_kh, qb1, queries, p_qh1);
    // 2) k2 (25) + q2 (100)
    fusedB<<<dim3(100, 1, 2), 256, smemB>>>(kb2, p_kh, p_k, qb2, p_qh1, p_qh2);
    // 3) q3 (100)
    convC<<<dim3(100, 1, 1), 256, smemB>>>(qb3, p_qh2, p_q);

    // 4) distance + log-softmax + prior
    const int smemF = (16000 + 32 * 81 + 200 + 32) * (int)sizeof(float);  // 75296 B
    cudaFuncSetAttribute(attn_final, cudaFuncAttributeMaxDynamicSharedMemorySize, smemF);
    attn_final<<<dim3(25, 16), 256, smemF>>>(p_q, p_k, prior, out);
}